// round 10
// baseline (speedup 1.0000x reference)
#include <cuda_runtime.h>
#include <cuda_fp16.h>
#include <cstdint>

// ---------------- problem constants ----------------
static constexpr int Bb = 4096, Ee = 16, Dd = 512, Hh = 2048;
static constexpr int TM = 64, TN = 128, KC = 64;      // CTA tile, k-chunk (64 fp16 = 128B rows)
static constexpr int EZ = 8;                          // experts per grid.z slice
static constexpr int ITERS = EZ * (Dd / KC);          // 8 experts * 8 k-chunks = 64
static constexpr int W_TILE_BYTES = 128 * 128;        // 128 rows * 128B = 16 KB
static constexpr int X_SUB_BYTES = 64 * 128;          // 64 rows * 128B = 8 KB per k-chunk
static constexpr int NTHREADS = 256;                  // 8 warps, 2(m) x 4(n), warp tile 32x32

// smem layout (per CTA ~102 KB -> 2 CTAs/SM)
static constexpr int X_OFF    = 0;                    // 8 * 8KB = 65536 (X resident, full K)
static constexpr int W_OFF    = 65536;                // 2 * 16KB = 32768
static constexpr int BIAS_OFF = 98304;                // 8*128*4 = 4096
static constexpr int SMEM_BYTES = 102400;

// ---------------- device scratch (allocation-free rule: __device__ globals) ----------------
__device__ __half d_Wh[(size_t)Ee * Hh * Dd];   // 32 MiB
__device__ __half d_Xh[(size_t)Bb * Dd];        //  4 MiB
__device__ float  d_bias2[Ee * Hh];             // 128 KiB
__device__ float  d_partial[(size_t)Bb * Hh];   // 32 MiB (z=1 partial sums)

// ---------------- helpers ----------------
__device__ __forceinline__ uint32_t smem_u32(const void* p) {
    uint32_t a;
    asm("{ .reg .u64 t; cvta.to.shared.u64 t, %1; cvt.u32.u64 %0, t; }" : "=r"(a) : "l"(p));
    return a;
}

#define SMEM_SWIZZLE_128B(off) ((off) ^ (((off) >> 3) & 0x70))

#define CP_ASYNC16(dst, src) \
    asm volatile("cp.async.cg.shared.global [%0], [%1], 16;" :: "r"(dst), "l"(src))
#define CP_ASYNC_COMMIT() asm volatile("cp.async.commit_group;" ::: "memory")

#define LDSM_X4(r, addr) \
    asm volatile("ldmatrix.sync.aligned.m8n8.x4.shared.b16 {%0,%1,%2,%3}, [%4];" \
                 : "=r"((r)[0]), "=r"((r)[1]), "=r"((r)[2]), "=r"((r)[3]) : "r"(addr))

__device__ __forceinline__ void mma16816(float* d, const uint32_t* a, uint32_t b0, uint32_t b1) {
    asm volatile("mma.sync.aligned.m16n8k16.row.col.f32.f16.f16.f32 "
                 "{%0,%1,%2,%3}, {%4,%5,%6,%7}, {%8,%9}, {%0,%1,%2,%3};"
                 : "+f"(d[0]), "+f"(d[1]), "+f"(d[2]), "+f"(d[3])
                 : "r"(a[0]), "r"(a[1]), "r"(a[2]), "r"(a[3]), "r"(b0), "r"(b1));
}

// W k-chunk tile -> smem stage (256 threads, 4x 16B each). Rows = h (128), 64 halfs per row.
__device__ __forceinline__ void load_w_tile(uint32_t sb, int h0, int ebase, int iter, int stage, int tid) {
    int e = ebase + (iter >> 3), kc = iter & 7;
    const __half* base = d_Wh + ((size_t)(e * Hh + h0) * Dd + kc * KC);
#pragma unroll
    for (int j = 0; j < 4; j++) {
        int q = tid + NTHREADS * j;            // 1024 chunks of 16B
        int r = q >> 3, i = q & 7;
        uint32_t off = (uint32_t)(r * 128 + i * 16);
        uint32_t dst = sb + W_OFF + stage * W_TILE_BYTES + SMEM_SWIZZLE_128B(off);
        const void* src = (const void*)(base + (size_t)r * Dd + i * 8);
        CP_ASYNC16(dst, src);
    }
}

// ---------------- pre-pass kernels ----------------
__global__ void cvt_w_kernel(const float* __restrict__ src) {
    int i = blockIdx.x * blockDim.x + threadIdx.x;     // one float4
    const int n4 = Ee * Hh * Dd / 4;
    if (i < n4) {
        float4 a = reinterpret_cast<const float4*>(src)[i];
        __half2* d = reinterpret_cast<__half2*>(d_Wh) + 2 * i;
        d[0] = __floats2half2_rn(a.x, a.y);
        d[1] = __floats2half2_rn(a.z, a.w);
    }
}
__global__ void cvt_x_kernel(const float* __restrict__ src) {
    int i = blockIdx.x * blockDim.x + threadIdx.x;
    const int n4 = Bb * Dd / 4;
    if (i < n4) {
        float4 a = reinterpret_cast<const float4*>(src)[i];
        __half2* d = reinterpret_cast<__half2*>(d_Xh) + 2 * i;
        d[0] = __floats2half2_rn(a.x, a.y);
        d[1] = __floats2half2_rn(a.z, a.w);
    }
}
// bias2[e,h] = b[e,h] - dot(c_e, W_h[e,h,:])  (one warp per output; W already fp16)
__global__ void bias2_kernel(const float* __restrict__ centers, const float* __restrict__ bvec) {
    int o = blockIdx.x * 8 + (threadIdx.x >> 5);
    int lane = threadIdx.x & 31;
    int e = o >> 11;                                   // / Hh
    const __half* w = d_Wh + (size_t)o * Dd;
    const float* ce = centers + e * Dd;
    float s = 0.f;
#pragma unroll
    for (int d = lane; d < Dd; d += 32) s += __half2float(w[d]) * ce[d];
#pragma unroll
    for (int m = 16; m; m >>= 1) s += __shfl_xor_sync(0xFFFFFFFFu, s, m);
    if (lane == 0) d_bias2[o] = bvec[o] - s;
}
// out += partial (deterministic combine of the z=1 slice)
__global__ void add_partial_kernel(float* __restrict__ out) {
    int i = blockIdx.x * blockDim.x + threadIdx.x;     // one float4
    const int n4 = Bb * Hh / 4;
    if (i < n4) {
        float4 a = reinterpret_cast<const float4*>(out)[i];
        float4 p = reinterpret_cast<const float4*>(d_partial)[i];
        a.x += p.x; a.y += p.y; a.z += p.z; a.w += p.w;
        reinterpret_cast<float4*>(out)[i] = a;
    }
}

// ---------------- main GEMM + fused relu/expert-reduce kernel ----------------
__global__ void __launch_bounds__(NTHREADS, 2) coop_main(float* __restrict__ out) {
    extern __shared__ char smem[];
    uint32_t sb = smem_u32(smem);
    int tid = threadIdx.x;
    int lane = tid & 31, wid = tid >> 5;
    int wm = wid >> 2, wn = wid & 3;                   // warp grid 2 (m) x 4 (n), warp tile 32x32
    int m0 = blockIdx.y * TM;
    int h0 = blockIdx.x * TN;
    int ebase = blockIdx.z * EZ;
    float* bias_sm = reinterpret_cast<float*>(smem + BIAS_OFF);

    // stage bias2 tile for this (h-block, expert slice)
#pragma unroll
    for (int i = tid; i < EZ * 128; i += NTHREADS)
        bias_sm[i] = d_bias2[(ebase + (i >> 7)) * Hh + h0 + (i & 127)];

    // X tile resident: 8 k-chunk sub-tiles of 64 rows x 64 halfs, SW128 (one group)
#pragma unroll 4
    for (int j = 0; j < 16; j++) {
        int q = tid + NTHREADS * j;                    // 4096 chunks of 16B
        int kc = q >> 9, r = (q >> 3) & 63, i = q & 7;
        uint32_t off = (uint32_t)(r * 128 + i * 16);
        uint32_t dst = sb + X_OFF + kc * X_SUB_BYTES + SMEM_SWIZZLE_128B(off);
        const void* src = (const void*)(d_Xh + ((size_t)(m0 + r) * Dd + kc * KC + i * 8));
        CP_ASYNC16(dst, src);
    }
    // W prologue: stage 0 (same group as X)
    load_w_tile(sb, h0, ebase, 0, 0, tid);
    CP_ASYNC_COMMIT();

    // per-lane ldmatrix address constants
    int t = lane >> 3, r = lane & 7;
    uint32_t xr = (uint32_t)r * 16;                    // swizzle XOR term (bits 4..6)
    uint32_t rowA[2], rowB[2];
#pragma unroll
    for (int mt = 0; mt < 2; mt++) rowA[mt] = (uint32_t)(wm * 32 + mt * 16 + (t & 1) * 8 + r) * 128;
#pragma unroll
    for (int np = 0; np < 2; np++) rowB[np] = (uint32_t)(wn * 32 + np * 16 + (t >> 1) * 8 + r) * 128;
    uint32_t kA = (uint32_t)(t >> 1) * 16;
    uint32_t kB = (uint32_t)(t & 1) * 16;

    float acc[2][4][4], sum[2][4][4];
#pragma unroll
    for (int mt = 0; mt < 2; mt++)
#pragma unroll
        for (int nt = 0; nt < 4; nt++)
#pragma unroll
            for (int i = 0; i < 4; i++) { acc[mt][nt][i] = 0.f; sum[mt][nt][i] = 0.f; }

    uint32_t aF[2][2][4], bF[2][2][4];                 // double-buffered fragments

    for (int it = 0; it < ITERS; it++) {
        asm volatile("cp.async.wait_group 0;" ::: "memory");
        __syncthreads();

        if (it + 1 < ITERS) {                          // prefetch next W stage (overlaps compute)
            load_w_tile(sb, h0, ebase, it + 1, (it + 1) & 1, tid);
            CP_ASYNC_COMMIT();
        }

        uint32_t xbase = sb + X_OFF + (uint32_t)(it & 7) * X_SUB_BYTES;
        uint32_t wbase = sb + W_OFF + (uint32_t)(it & 1) * W_TILE_BYTES;

        // prime ks=0 fragments
#pragma unroll
        for (int mt = 0; mt < 2; mt++) LDSM_X4(aF[0][mt], xbase + rowA[mt] + (kA ^ xr));
#pragma unroll
        for (int np = 0; np < 2; np++) LDSM_X4(bF[0][np], wbase + rowB[np] + (kB ^ xr));

#pragma unroll
        for (int ks = 0; ks < 4; ks++) {
            int cur = ks & 1, nxt = cur ^ 1;
            if (ks < 3) {                              // prefetch ks+1 before consuming ks
                uint32_t kk = (uint32_t)(ks + 1) * 32;
#pragma unroll
                for (int mt = 0; mt < 2; mt++) LDSM_X4(aF[nxt][mt], xbase + rowA[mt] + ((kk + kA) ^ xr));
#pragma unroll
                for (int np = 0; np < 2; np++) LDSM_X4(bF[nxt][np], wbase + rowB[np] + ((kk + kB) ^ xr));
            }
#pragma unroll
            for (int mt = 0; mt < 2; mt++)
#pragma unroll
                for (int np = 0; np < 2; np++) {
                    mma16816(acc[mt][2 * np],     aF[cur][mt], bF[cur][np][0], bF[cur][np][1]);
                    mma16816(acc[mt][2 * np + 1], aF[cur][mt], bF[cur][np][2], bF[cur][np][3]);
                }
        }

        if ((it & 7) == 7) {                           // expert boundary: fold
            int e = it >> 3;
            const float* bp = bias_sm + e * 128 + wn * 32 + 2 * (lane & 3);
#pragma unroll
            for (int nt = 0; nt < 4; nt++) {
                float b0 = bp[nt * 8];
                float b1 = bp[nt * 8 + 1];
#pragma unroll
                for (int mt = 0; mt < 2; mt++) {
                    sum[mt][nt][0] += fmaxf(acc[mt][nt][0] + b0, 0.f);
                    sum[mt][nt][1] += fmaxf(acc[mt][nt][1] + b1, 0.f);
                    sum[mt][nt][2] += fmaxf(acc[mt][nt][2] + b0, 0.f);
                    sum[mt][nt][3] += fmaxf(acc[mt][nt][3] + b1, 0.f);
                    acc[mt][nt][0] = 0.f; acc[mt][nt][1] = 0.f;
                    acc[mt][nt][2] = 0.f; acc[mt][nt][3] = 0.f;
                }
            }
        }
    }

    // write out [64 x 128] fp32 (z=0 -> out, z=1 -> partial buffer)
    float* obase = blockIdx.z ? d_partial : out;
#pragma unroll
    for (int mt = 0; mt < 2; mt++) {
        int mrow = m0 + wm * 32 + mt * 16 + (lane >> 2);
#pragma unroll
        for (int nt = 0; nt < 4; nt++) {
            int col = h0 + wn * 32 + nt * 8 + 2 * (lane & 3);
            float2 v0 = make_float2(sum[mt][nt][0], sum[mt][nt][1]);
            float2 v1 = make_float2(sum[mt][nt][2], sum[mt][nt][3]);
            *reinterpret_cast<float2*>(obase + (size_t)mrow * Hh + col) = v0;
            *reinterpret_cast<float2*>(obase + (size_t)(mrow + 8) * Hh + col) = v1;
        }
    }
}

// ---------------- launch ----------------
extern "C" void kernel_launch(void* const* d_in, const int* in_sizes, int n_in,
                              void* d_out, int out_size) {
    const float* x  = (const float*)d_in[0];   // [4096, 512]
    const float* c  = (const float*)d_in[1];   // [16, 512]
    const float* W  = (const float*)d_in[2];   // [16, 2048, 512]
    const float* bv = (const float*)d_in[3];   // [16, 2048]
    float* out = (float*)d_out;                // [4096, 2048]

    cudaFuncSetAttribute(coop_main, cudaFuncAttributeMaxDynamicSharedMemorySize, SMEM_BYTES);

    cvt_w_kernel<<<(Ee * Hh * Dd / 4 + 255) / 256, 256>>>(W);
    cvt_x_kernel<<<(Bb * Dd / 4 + 255) / 256, 256>>>(x);
    bias2_kernel<<<Ee * Hh / 8, 256>>>(c, bv);
    coop_main<<<dim3(Hh / TN, Bb / TM, 2), NTHREADS, SMEM_BYTES>>>(out);
    add_partial_kernel<<<(Bb * Hh / 4 + 255) / 256, 256>>>(out);
}

// round 11
// speedup vs baseline: 1.0253x; 1.0253x over previous
#include <cuda_runtime.h>
#include <cuda_fp16.h>
#include <cstdint>

// ---------------- problem constants ----------------
static constexpr int Bb = 4096, Ee = 16, Dd = 512, Hh = 2048;
static constexpr int TM = 64, TN = 128, KC = 64;      // CTA tile, k-chunk (64 fp16 = 128B rows)
static constexpr int NSTAGE = 3;                      // W pipeline depth (prefetch distance 2)
static constexpr int ITERS = Ee * (Dd / KC);          // 16 experts * 8 k-chunks = 128
static constexpr int W_TILE_BYTES = 128 * 128;        // 128 rows * 128B = 16 KB
static constexpr int X_SUB_BYTES = 64 * 128;          // 64 rows * 128B = 8 KB per k-chunk
static constexpr int NTHREADS = 256;                  // 8 warps, 2(m) x 4(n), warp tile 32x32

// smem layout (per CTA 112 KB -> 2 CTAs/SM)
static constexpr int X_OFF    = 0;                    // 8 * 8KB = 65536 (X resident, full K)
static constexpr int W_OFF    = 65536;                // 3 * 16KB = 49152
static constexpr int SMEM_BYTES = 114688;             // 112 KB

// ---------------- device scratch (allocation-free rule: __device__ globals) ----------------
__device__ __half d_Wh[(size_t)Ee * Hh * Dd];   // 32 MiB
__device__ __half d_Xh[(size_t)Bb * Dd];        //  4 MiB
__device__ float  d_bias2[Ee * Hh];             // 128 KiB

// ---------------- helpers ----------------
__device__ __forceinline__ uint32_t smem_u32(const void* p) {
    uint32_t a;
    asm("{ .reg .u64 t; cvta.to.shared.u64 t, %1; cvt.u32.u64 %0, t; }" : "=r"(a) : "l"(p));
    return a;
}

#define SMEM_SWIZZLE_128B(off) ((off) ^ (((off) >> 3) & 0x70))

#define CP_ASYNC16(dst, src) \
    asm volatile("cp.async.cg.shared.global [%0], [%1], 16;" :: "r"(dst), "l"(src))
#define CP_ASYNC_COMMIT() asm volatile("cp.async.commit_group;" ::: "memory")

#define LDSM_X4(r, addr) \
    asm volatile("ldmatrix.sync.aligned.m8n8.x4.shared.b16 {%0,%1,%2,%3}, [%4];" \
                 : "=r"((r)[0]), "=r"((r)[1]), "=r"((r)[2]), "=r"((r)[3]) : "r"(addr))

__device__ __forceinline__ void mma16816(float* d, const uint32_t* a, uint32_t b0, uint32_t b1) {
    asm volatile("mma.sync.aligned.m16n8k16.row.col.f32.f16.f16.f32 "
                 "{%0,%1,%2,%3}, {%4,%5,%6,%7}, {%8,%9}, {%0,%1,%2,%3};"
                 : "+f"(d[0]), "+f"(d[1]), "+f"(d[2]), "+f"(d[3])
                 : "r"(a[0]), "r"(a[1]), "r"(a[2]), "r"(a[3]), "r"(b0), "r"(b1));
}

// W k-chunk tile -> smem stage (256 threads, 4x 16B each). Rows = h (128), 64 halfs per row.
__device__ __forceinline__ void load_w_tile(uint32_t sb, int h0, int iter, int stage, int tid) {
    int e = iter >> 3, kc = iter & 7;
    const __half* base = d_Wh + ((size_t)(e * Hh + h0) * Dd + kc * KC);
#pragma unroll
    for (int j = 0; j < 4; j++) {
        int q = tid + NTHREADS * j;            // 1024 chunks of 16B
        int r = q >> 3, i = q & 7;
        uint32_t off = (uint32_t)(r * 128 + i * 16);
        uint32_t dst = sb + W_OFF + stage * W_TILE_BYTES + SMEM_SWIZZLE_128B(off);
        const void* src = (const void*)(base + (size_t)r * Dd + i * 8);
        CP_ASYNC16(dst, src);
    }
}

// ---------------- pre-pass kernels ----------------
__global__ void cvt_w_kernel(const float* __restrict__ src) {
    int i = blockIdx.x * blockDim.x + threadIdx.x;     // one float4
    const int n4 = Ee * Hh * Dd / 4;
    if (i < n4) {
        float4 a = reinterpret_cast<const float4*>(src)[i];
        __half2* d = reinterpret_cast<__half2*>(d_Wh) + 2 * i;
        d[0] = __floats2half2_rn(a.x, a.y);
        d[1] = __floats2half2_rn(a.z, a.w);
    }
}
__global__ void cvt_x_kernel(const float* __restrict__ src) {
    int i = blockIdx.x * blockDim.x + threadIdx.x;
    const int n4 = Bb * Dd / 4;
    if (i < n4) {
        float4 a = reinterpret_cast<const float4*>(src)[i];
        __half2* d = reinterpret_cast<__half2*>(d_Xh) + 2 * i;
        d[0] = __floats2half2_rn(a.x, a.y);
        d[1] = __floats2half2_rn(a.z, a.w);
    }
}
// bias2[e,h] = b[e,h] - dot(c_e, W_h[e,h,:])  (one warp per output; W already fp16)
__global__ void bias2_kernel(const float* __restrict__ centers, const float* __restrict__ bvec) {
    int o = blockIdx.x * 8 + (threadIdx.x >> 5);
    int lane = threadIdx.x & 31;
    int e = o >> 11;                                   // / Hh
    const __half* w = d_Wh + (size_t)o * Dd;
    const float* ce = centers + e * Dd;
    float s = 0.f;
#pragma unroll
    for (int d = lane; d < Dd; d += 32) s += __half2float(w[d]) * ce[d];
#pragma unroll
    for (int m = 16; m; m >>= 1) s += __shfl_xor_sync(0xFFFFFFFFu, s, m);
    if (lane == 0) d_bias2[o] = bvec[o] - s;
}

// ---------------- main GEMM + fused relu/expert-reduce kernel ----------------
__global__ void __launch_bounds__(NTHREADS, 2) coop_main(float* __restrict__ out) {
    extern __shared__ char smem[];
    uint32_t sb = smem_u32(smem);
    int tid = threadIdx.x;
    int lane = tid & 31, wid = tid >> 5;
    int wm = wid >> 2, wn = wid & 3;                   // warp grid 2 (m) x 4 (n), warp tile 32x32
    int m0 = blockIdx.y * TM;
    int h0 = blockIdx.x * TN;

    // X tile resident: 8 k-chunk sub-tiles of 64 rows x 64 halfs, SW128 (group with W stage 0)
#pragma unroll 4
    for (int j = 0; j < 16; j++) {
        int q = tid + NTHREADS * j;                    // 4096 chunks of 16B
        int kc = q >> 9, r = (q >> 3) & 63, i = q & 7;
        uint32_t off = (uint32_t)(r * 128 + i * 16);
        uint32_t dst = sb + X_OFF + kc * X_SUB_BYTES + SMEM_SWIZZLE_128B(off);
        const void* src = (const void*)(d_Xh + ((size_t)(m0 + r) * Dd + kc * KC + i * 8));
        CP_ASYNC16(dst, src);
    }
    // W prologue: stage 0 (same group as X), then stage 1 (own group)
    load_w_tile(sb, h0, 0, 0, tid);
    CP_ASYNC_COMMIT();
    load_w_tile(sb, h0, 1, 1, tid);
    CP_ASYNC_COMMIT();

    // per-lane ldmatrix address constants
    int t = lane >> 3, r = lane & 7;
    uint32_t xr = (uint32_t)r * 16;                    // swizzle XOR term (bits 4..6)
    uint32_t rowA[2], rowB[2];
#pragma unroll
    for (int mt = 0; mt < 2; mt++) rowA[mt] = (uint32_t)(wm * 32 + mt * 16 + (t & 1) * 8 + r) * 128;
#pragma unroll
    for (int np = 0; np < 2; np++) rowB[np] = (uint32_t)(wn * 32 + np * 16 + (t >> 1) * 8 + r) * 128;
    uint32_t kA = (uint32_t)(t >> 1) * 16;
    uint32_t kB = (uint32_t)(t & 1) * 16;

    float acc[2][4][4], sum[2][4][4];
#pragma unroll
    for (int mt = 0; mt < 2; mt++)
#pragma unroll
        for (int nt = 0; nt < 4; nt++)
#pragma unroll
            for (int i = 0; i < 4; i++) { acc[mt][nt][i] = 0.f; sum[mt][nt][i] = 0.f; }

    uint32_t aF[2][2][4], bF[2][2][4];                 // double-buffered fragments

    for (int it = 0; it < ITERS; it++) {
        // stage(it) must be complete; with distance-2 prefetch the newer group may stay in flight
        if (it + 1 < ITERS) asm volatile("cp.async.wait_group 1;" ::: "memory");
        else                asm volatile("cp.async.wait_group 0;" ::: "memory");
        __syncthreads();

        if (it + 2 < ITERS) {                          // prefetch stage it+2 (2 iters of slack)
            load_w_tile(sb, h0, it + 2, (it + 2) % NSTAGE, tid);
            CP_ASYNC_COMMIT();
        }

        uint32_t xbase = sb + X_OFF + (uint32_t)(it & 7) * X_SUB_BYTES;
        uint32_t wbase = sb + W_OFF + (uint32_t)(it % NSTAGE) * W_TILE_BYTES;

        // prime ks=0 fragments
#pragma unroll
        for (int mt = 0; mt < 2; mt++) LDSM_X4(aF[0][mt], xbase + rowA[mt] + (kA ^ xr));
#pragma unroll
        for (int np = 0; np < 2; np++) LDSM_X4(bF[0][np], wbase + rowB[np] + (kB ^ xr));

#pragma unroll
        for (int ks = 0; ks < 4; ks++) {
            int cur = ks & 1, nxt = cur ^ 1;
            if (ks < 3) {                              // prefetch ks+1 before consuming ks
                uint32_t kk = (uint32_t)(ks + 1) * 32;
#pragma unroll
                for (int mt = 0; mt < 2; mt++) LDSM_X4(aF[nxt][mt], xbase + rowA[mt] + ((kk + kA) ^ xr));
#pragma unroll
                for (int np = 0; np < 2; np++) LDSM_X4(bF[nxt][np], wbase + rowB[np] + ((kk + kB) ^ xr));
            }
#pragma unroll
            for (int mt = 0; mt < 2; mt++)
#pragma unroll
                for (int np = 0; np < 2; np++) {
                    mma16816(acc[mt][2 * np],     aF[cur][mt], bF[cur][np][0], bF[cur][np][1]);
                    mma16816(acc[mt][2 * np + 1], aF[cur][mt], bF[cur][np][2], bF[cur][np][3]);
                }
        }

        if ((it & 7) == 7) {                           // expert boundary: fold (bias from L2)
            int e = it >> 3;
            const float* bp = d_bias2 + (size_t)e * Hh + h0 + wn * 32 + 2 * (lane & 3);
#pragma unroll
            for (int nt = 0; nt < 4; nt++) {
                float2 bv = __ldg(reinterpret_cast<const float2*>(bp + nt * 8));
#pragma unroll
                for (int mt = 0; mt < 2; mt++) {
                    sum[mt][nt][0] += fmaxf(acc[mt][nt][0] + bv.x, 0.f);
                    sum[mt][nt][1] += fmaxf(acc[mt][nt][1] + bv.y, 0.f);
                    sum[mt][nt][2] += fmaxf(acc[mt][nt][2] + bv.x, 0.f);
                    sum[mt][nt][3] += fmaxf(acc[mt][nt][3] + bv.y, 0.f);
                    acc[mt][nt][0] = 0.f; acc[mt][nt][1] = 0.f;
                    acc[mt][nt][2] = 0.f; acc[mt][nt][3] = 0.f;
                }
            }
        }
    }

    // write out [64 x 128] fp32
#pragma unroll
    for (int mt = 0; mt < 2; mt++) {
        int mrow = m0 + wm * 32 + mt * 16 + (lane >> 2);
#pragma unroll
        for (int nt = 0; nt < 4; nt++) {
            int col = h0 + wn * 32 + nt * 8 + 2 * (lane & 3);
            float2 v0 = make_float2(sum[mt][nt][0], sum[mt][nt][1]);
            float2 v1 = make_float2(sum[mt][nt][2], sum[mt][nt][3]);
            *reinterpret_cast<float2*>(out + (size_t)mrow * Hh + col) = v0;
            *reinterpret_cast<float2*>(out + (size_t)(mrow + 8) * Hh + col) = v1;
        }
    }
}

// ---------------- launch ----------------
extern "C" void kernel_launch(void* const* d_in, const int* in_sizes, int n_in,
                              void* d_out, int out_size) {
    const float* x  = (const float*)d_in[0];   // [4096, 512]
    const float* c  = (const float*)d_in[1];   // [16, 512]
    const float* W  = (const float*)d_in[2];   // [16, 2048, 512]
    const float* bv = (const float*)d_in[3];   // [16, 2048]
    float* out = (float*)d_out;                // [4096, 2048]

    cudaFuncSetAttribute(coop_main, cudaFuncAttributeMaxDynamicSharedMemorySize, SMEM_BYTES);

    cvt_w_kernel<<<(Ee * Hh * Dd / 4 + 255) / 256, 256>>>(W);
    cvt_x_kernel<<<(Bb * Dd / 4 + 255) / 256, 256>>>(x);
    bias2_kernel<<<Ee * Hh / 8, 256>>>(c, bv);
    coop_main<<<dim3(Hh / TN, Bb / TM), NTHREADS, SMEM_BYTES>>>(out);
}

// round 15
// speedup vs baseline: 1.1720x; 1.1432x over previous
#include <cuda_runtime.h>
#include <cuda_fp16.h>
#include <cstdint>

// ---------------- problem constants ----------------
static constexpr int Bb = 4096, Ee = 16, Dd = 512, Hh = 2048;
static constexpr int TM = 64, TN = 128, KC = 64;      // CTA tile, k-chunk (64 fp16 = 128B rows)
static constexpr int ITERS = Ee * (Dd / KC);          // 16 experts * 8 k-chunks = 128
static constexpr int W_TILE_BYTES = 128 * 128;        // 128 rows * 128B = 16 KB
static constexpr int X_SUB_BYTES = 64 * 128;          // 64 rows * 128B = 8 KB per k-chunk
static constexpr int NTHREADS = 128;                  // 4 warps, 1(m) x 4(n), warp tile 64x32

// smem layout (per CTA 104 KB -> 2 CTAs/SM; 256 threads/SM -> up to 255 regs/thread)
static constexpr int X_OFF    = 0;                    // 8 * 8KB = 65536 (X resident, full K)
static constexpr int W_OFF    = 65536;                // 2 * 16KB = 32768
static constexpr int BIAS_OFF = 98304;                // 16*128*4 = 8192
static constexpr int SMEM_BYTES = 106496;

// ---------------- device scratch (allocation-free rule: __device__ globals) ----------------
__device__ __half d_Wh[(size_t)Ee * Hh * Dd];   // 32 MiB
__device__ __half d_Xh[(size_t)Bb * Dd];        //  4 MiB
__device__ float  d_bias2[Ee * Hh];             // 128 KiB

// ---------------- helpers ----------------
__device__ __forceinline__ uint32_t smem_u32(const void* p) {
    uint32_t a;
    asm("{ .reg .u64 t; cvta.to.shared.u64 t, %1; cvt.u32.u64 %0, t; }" : "=r"(a) : "l"(p));
    return a;
}

#define SMEM_SWIZZLE_128B(off) ((off) ^ (((off) >> 3) & 0x70))

#define CP_ASYNC16(dst, src) \
    asm volatile("cp.async.cg.shared.global [%0], [%1], 16;" :: "r"(dst), "l"(src))
#define CP_ASYNC_COMMIT() asm volatile("cp.async.commit_group;" ::: "memory")

#define LDSM_X4(r, addr) \
    asm volatile("ldmatrix.sync.aligned.m8n8.x4.shared.b16 {%0,%1,%2,%3}, [%4];" \
                 : "=r"((r)[0]), "=r"((r)[1]), "=r"((r)[2]), "=r"((r)[3]) : "r"(addr))

__device__ __forceinline__ void mma16816(float* d, const uint32_t* a, uint32_t b0, uint32_t b1) {
    asm volatile("mma.sync.aligned.m16n8k16.row.col.f32.f16.f16.f32 "
                 "{%0,%1,%2,%3}, {%4,%5,%6,%7}, {%8,%9}, {%0,%1,%2,%3};"
                 : "+f"(d[0]), "+f"(d[1]), "+f"(d[2]), "+f"(d[3])
                 : "r"(a[0]), "r"(a[1]), "r"(a[2]), "r"(a[3]), "r"(b0), "r"(b1));
}

// W k-chunk tile -> smem stage (128 threads, 8x 16B each). Rows = h (128), 64 halfs per row.
__device__ __forceinline__ void load_w_tile(uint32_t sb, int h0, int iter, int stage, int tid) {
    int e = iter >> 3, kc = iter & 7;
    const __half* base = d_Wh + ((size_t)(e * Hh + h0) * Dd + kc * KC);
#pragma unroll
    for (int j = 0; j < 8; j++) {
        int q = tid + NTHREADS * j;            // 1024 chunks of 16B
        int r = q >> 3, i = q & 7;
        uint32_t off = (uint32_t)(r * 128 + i * 16);
        uint32_t dst = sb + W_OFF + stage * W_TILE_BYTES + SMEM_SWIZZLE_128B(off);
        const void* src = (const void*)(base + (size_t)r * Dd + i * 8);
        CP_ASYNC16(dst, src);
    }
}

// ---------------- pre-pass kernels ----------------
__global__ void cvt_w_kernel(const float* __restrict__ src) {
    int i = blockIdx.x * blockDim.x + threadIdx.x;     // one float4
    const int n4 = Ee * Hh * Dd / 4;
    if (i < n4) {
        float4 a = reinterpret_cast<const float4*>(src)[i];
        __half2* d = reinterpret_cast<__half2*>(d_Wh) + 2 * i;
        d[0] = __floats2half2_rn(a.x, a.y);
        d[1] = __floats2half2_rn(a.z, a.w);
    }
}
__global__ void cvt_x_kernel(const float* __restrict__ src) {
    int i = blockIdx.x * blockDim.x + threadIdx.x;
    const int n4 = Bb * Dd / 4;
    if (i < n4) {
        float4 a = reinterpret_cast<const float4*>(src)[i];
        __half2* d = reinterpret_cast<__half2*>(d_Xh) + 2 * i;
        d[0] = __floats2half2_rn(a.x, a.y);
        d[1] = __floats2half2_rn(a.z, a.w);
    }
}
// bias2[e,h] = b[e,h] - dot(c_e, W_h[e,h,:])  (one warp per output; W already fp16)
__global__ void bias2_kernel(const float* __restrict__ centers, const float* __restrict__ bvec) {
    int o = blockIdx.x * 8 + (threadIdx.x >> 5);
    int lane = threadIdx.x & 31;
    int e = o >> 11;                                   // / Hh
    const __half* w = d_Wh + (size_t)o * Dd;
    const float* ce = centers + e * Dd;
    float s = 0.f;
#pragma unroll
    for (int d = lane; d < Dd; d += 32) s += __half2float(w[d]) * ce[d];
#pragma unroll
    for (int m = 16; m; m >>= 1) s += __shfl_xor_sync(0xFFFFFFFFu, s, m);
    if (lane == 0) d_bias2[o] = bvec[o] - s;
}

// ---------------- main GEMM + fused relu/expert-reduce kernel ----------------
__global__ void __launch_bounds__(NTHREADS, 2) coop_main(float* __restrict__ out) {
    extern __shared__ char smem[];
    uint32_t sb = smem_u32(smem);
    int tid = threadIdx.x;
    int lane = tid & 31, wid = tid >> 5;
    int wn = wid;                                      // warp grid 1(m) x 4(n), warp tile 64x32
    int m0 = blockIdx.y * TM;
    int h0 = blockIdx.x * TN;
    float* bias_sm = reinterpret_cast<float*>(smem + BIAS_OFF);

    // stage bias2 tile for this h-block
#pragma unroll
    for (int i = tid; i < Ee * 128; i += NTHREADS)
        bias_sm[i] = d_bias2[(i >> 7) * Hh + h0 + (i & 127)];

    // X tile resident: 8 k-chunk sub-tiles of 64 rows x 64 halfs, SW128 (group with W stage 0)
#pragma unroll 8
    for (int j = 0; j < 32; j++) {
        int q = tid + NTHREADS * j;                    // 4096 chunks of 16B
        int kc = q >> 9, r = (q >> 3) & 63, i = q & 7;
        uint32_t off = (uint32_t)(r * 128 + i * 16);
        uint32_t dst = sb + X_OFF + kc * X_SUB_BYTES + SMEM_SWIZZLE_128B(off);
        const void* src = (const void*)(d_Xh + ((size_t)(m0 + r) * Dd + kc * KC + i * 8));
        CP_ASYNC16(dst, src);
    }
    // W prologue: stage 0 (same group as X)
    load_w_tile(sb, h0, 0, 0, tid);
    CP_ASYNC_COMMIT();

    // per-lane ldmatrix address constants
    int t = lane >> 3, r = lane & 7;
    uint32_t xr = (uint32_t)r * 16;                    // swizzle XOR term (bits 4..6)
    uint32_t rowA[4], rowB[2];
#pragma unroll
    for (int mt = 0; mt < 4; mt++) rowA[mt] = (uint32_t)(mt * 16 + (t & 1) * 8 + r) * 128;
#pragma unroll
    for (int np = 0; np < 2; np++) rowB[np] = (uint32_t)(wn * 32 + np * 16 + (t >> 1) * 8 + r) * 128;
    uint32_t kA = (uint32_t)(t >> 1) * 16;
    uint32_t kB = (uint32_t)(t & 1) * 16;

    float acc[4][4][4], sum[4][4][4];
#pragma unroll
    for (int mt = 0; mt < 4; mt++)
#pragma unroll
        for (int nt = 0; nt < 4; nt++)
#pragma unroll
            for (int i = 0; i < 4; i++) { acc[mt][nt][i] = 0.f; sum[mt][nt][i] = 0.f; }

    uint32_t aF[2][4][4], bF[2][2][4];                 // double-buffered fragments

    for (int it = 0; it < ITERS; it++) {
        asm volatile("cp.async.wait_group 0;" ::: "memory");
        __syncthreads();

        if (it + 1 < ITERS) {                          // prefetch next W stage (overlaps compute)
            load_w_tile(sb, h0, it + 1, (it + 1) & 1, tid);
            CP_ASYNC_COMMIT();
        }

        uint32_t xbase = sb + X_OFF + (uint32_t)(it & 7) * X_SUB_BYTES;
        uint32_t wbase = sb + W_OFF + (uint32_t)(it & 1) * W_TILE_BYTES;

        // prime ks=0 fragments
#pragma unroll
        for (int mt = 0; mt < 4; mt++) LDSM_X4(aF[0][mt], xbase + rowA[mt] + (kA ^ xr));
#pragma unroll
        for (int np = 0; np < 2; np++) LDSM_X4(bF[0][np], wbase + rowB[np] + (kB ^ xr));

#pragma unroll
        for (int ks = 0; ks < 4; ks++) {
            int cur = ks & 1, nxt = cur ^ 1;
            if (ks < 3) {                              // prefetch ks+1 before consuming ks
                uint32_t kk = (uint32_t)(ks + 1) * 32;
#pragma unroll
                for (int mt = 0; mt < 4; mt++) LDSM_X4(aF[nxt][mt], xbase + rowA[mt] + ((kk + kA) ^ xr));
#pragma unroll
                for (int np = 0; np < 2; np++) LDSM_X4(bF[nxt][np], wbase + rowB[np] + ((kk + kB) ^ xr));
            }
#pragma unroll
            for (int mt = 0; mt < 4; mt++)
#pragma unroll
                for (int np = 0; np < 2; np++) {
                    mma16816(acc[mt][2 * np],     aF[cur][mt], bF[cur][np][0], bF[cur][np][1]);
                    mma16816(acc[mt][2 * np + 1], aF[cur][mt], bF[cur][np][2], bF[cur][np][3]);
                }
        }

        if ((it & 7) == 7) {                           // expert boundary: fold
            int e = it >> 3;
            const float* bp = bias_sm + e * 128 + wn * 32 + 2 * (lane & 3);
#pragma unroll
            for (int nt = 0; nt < 4; nt++) {
                float b0 = bp[nt * 8];
                float b1 = bp[nt * 8 + 1];
#pragma unroll
                for (int mt = 0; mt < 4; mt++) {
                    sum[mt][nt][0] += fmaxf(acc[mt][nt][0] + b0, 0.f);
                    sum[mt][nt][1] += fmaxf(acc[mt][nt][1] + b1, 0.f);
                    sum[mt][nt][2] += fmaxf(acc[mt][nt][2] + b0, 0.f);
                    sum[mt][nt][3] += fmaxf(acc[mt][nt][3] + b1, 0.f);
                    acc[mt][nt][0] = 0.f; acc[mt][nt][1] = 0.f;
                    acc[mt][nt][2] = 0.f; acc[mt][nt][3] = 0.f;
                }
            }
        }
    }

    // write out [64 x 128] fp32
#pragma unroll
    for (int mt = 0; mt < 4; mt++) {
        int mrow = m0 + mt * 16 + (lane >> 2);
#pragma unroll
        for (int nt = 0; nt < 4; nt++) {
            int col = h0 + wn * 32 + nt * 8 + 2 * (lane & 3);
            float2 v0 = make_float2(sum[mt][nt][0], sum[mt][nt][1]);
            float2 v1 = make_float2(sum[mt][nt][2], sum[mt][nt][3]);
            *reinterpret_cast<float2*>(out + (size_t)mrow * Hh + col) = v0;
            *reinterpret_cast<float2*>(out + (size_t)(mrow + 8) * Hh + col) = v1;
        }
    }
}

// ---------------- launch ----------------
extern "C" void kernel_launch(void* const* d_in, const int* in_sizes, int n_in,
                              void* d_out, int out_size) {
    const float* x  = (const float*)d_in[0];   // [4096, 512]
    const float* c  = (const float*)d_in[1];   // [16, 512]
    const float* W  = (const float*)d_in[2];   // [16, 2048, 512]
    const float* bv = (const float*)d_in[3];   // [16, 2048]
    float* out = (float*)d_out;                // [4096, 2048]

    cudaFuncSetAttribute(coop_main, cudaFuncAttributeMaxDynamicSharedMemorySize, SMEM_BYTES);

    cvt_w_kernel<<<(Ee * Hh * Dd / 4 + 255) / 256, 256>>>(W);
    cvt_x_kernel<<<(Bb * Dd / 4 + 255) / 256, 256>>>(x);
    bias2_kernel<<<Ee * Hh / 8, 256>>>(c, bv);
    coop_main<<<dim3(Hh / TN, Bb / TM), NTHREADS, SMEM_BYTES>>>(out);
}